// round 5
// baseline (speedup 1.0000x reference)
#include <cuda_runtime.h>

#define SEQ    1024
#define BATCH  64
#define UNITS  512
#define ORDER  128
#define INDIM  512

// scratch (device global: no allocation allowed)
__device__ float g_xe[BATCH * SEQ];

// ---------------------------------------------------------------------------
// f32x2 helpers (Blackwell packed fp32 pipe)
// ---------------------------------------------------------------------------
__device__ __forceinline__ void ffma2(unsigned long long& d,
                                      unsigned long long a,
                                      unsigned long long b) {
    asm("fma.rn.f32x2 %0, %1, %2, %0;" : "+l"(d) : "l"(a), "l"(b));
}
__device__ __forceinline__ unsigned long long pack2(float lo, float hi) {
    unsigned long long r;
    asm("mov.b64 %0, {%1, %2};" : "=l"(r) : "f"(lo), "f"(hi));
    return r;
}
__device__ __forceinline__ float hsum2(unsigned long long v) {
    float lo, hi;
    asm("mov.b64 {%0, %1}, %2;" : "=f"(lo), "=f"(hi) : "l"(v));
    return lo + hi;
}

// ---------------------------------------------------------------------------
// Kernel 1: xe[b,t] = x[b,t,:] @ input_encoders. One warp per row.
// ---------------------------------------------------------------------------
__global__ void __launch_bounds__(256) xe_kernel(const float* __restrict__ x,
                                                 const float* __restrict__ ie) {
    const int warp = threadIdx.x >> 5;
    const int lane = threadIdx.x & 31;
    const int row  = blockIdx.x * 8 + warp;   // [0, 65536)
    const float* xr = x + (size_t)row * INDIM;
    float s = 0.f;
#pragma unroll
    for (int k = lane; k < INDIM; k += 32) s += xr[k] * ie[k];
#pragma unroll
    for (int o = 16; o > 0; o >>= 1) s += __shfl_down_sync(0xffffffffu, s, o);
    if (lane == 0) g_xe[row] = s;
}

// ---------------------------------------------------------------------------
// Kernel 2: prex = X @ input_kernel  (M=65536, N=512, K=512, fp32 -> FFMA2)
// BM=128, BN=128, BK=16, 256 threads, 8x8 micro-tile (n packed in f32x2).
// ---------------------------------------------------------------------------
__global__ void __launch_bounds__(256, 2) gemm_kernel(const float* __restrict__ A,
                                                      const float* __restrict__ B,
                                                      float* __restrict__ C) {
    __shared__ float As[16][132];   // [k][m], padded (528B rows, 16B aligned)
    __shared__ float Bs[16][128];   // [k][n]
    const int m0  = blockIdx.x * 128;
    const int n0  = blockIdx.y * 128;
    const int tid = threadIdx.x;
    const int tx  = tid & 15;       // n dir, 8 cols each
    const int ty  = tid >> 4;       // m dir, 8 rows each

    unsigned long long acc[8][4];   // [m][n-pair], each f32x2 over (2n, 2n+1)
#pragma unroll
    for (int i = 0; i < 8; i++)
#pragma unroll
        for (int j = 0; j < 4; j++) acc[i][j] = 0ull;

    for (int k0 = 0; k0 < 512; k0 += 16) {
        // stage A (128x16, transposed into As[k][m])
#pragma unroll
        for (int i = 0; i < 2; i++) {
            int idx = tid + i * 256;          // 0..511
            int row = idx >> 2;               // 0..127
            int c4  = (idx & 3) << 2;         // 0,4,8,12
            float4 v = *reinterpret_cast<const float4*>(&A[(size_t)(m0 + row) * 512 + k0 + c4]);
            As[c4 + 0][row] = v.x; As[c4 + 1][row] = v.y;
            As[c4 + 2][row] = v.z; As[c4 + 3][row] = v.w;
        }
        // stage B (16x128)
#pragma unroll
        for (int i = 0; i < 2; i++) {
            int idx = tid + i * 256;          // 0..511
            int row = idx >> 5;               // 0..15
            int c4  = (idx & 31) << 2;        // 0..124
            *reinterpret_cast<float4*>(&Bs[row][c4]) =
                *reinterpret_cast<const float4*>(&B[(size_t)(k0 + row) * 512 + n0 + c4]);
        }
        __syncthreads();
#pragma unroll
        for (int k = 0; k < 16; k++) {
            ulonglong2 b01 = *reinterpret_cast<const ulonglong2*>(&Bs[k][tx * 8]);
            ulonglong2 b23 = *reinterpret_cast<const ulonglong2*>(&Bs[k][tx * 8 + 4]);
            float4 ra0 = *reinterpret_cast<const float4*>(&As[k][ty * 8]);
            float4 ra1 = *reinterpret_cast<const float4*>(&As[k][ty * 8 + 4]);
            float rm[8] = {ra0.x, ra0.y, ra0.z, ra0.w, ra1.x, ra1.y, ra1.z, ra1.w};
#pragma unroll
            for (int i = 0; i < 8; i++) {
                unsigned long long rp = pack2(rm[i], rm[i]);
                ffma2(acc[i][0], rp, b01.x);
                ffma2(acc[i][1], rp, b01.y);
                ffma2(acc[i][2], rp, b23.x);
                ffma2(acc[i][3], rp, b23.y);
            }
        }
        __syncthreads();
    }
#pragma unroll
    for (int i = 0; i < 8; i++) {
        size_t base = (size_t)(m0 + ty * 8 + i) * 512 + n0 + tx * 8;
        ulonglong2 o0; o0.x = acc[i][0]; o0.y = acc[i][1];
        ulonglong2 o1; o1.x = acc[i][2]; o1.y = acc[i][3];
        *reinterpret_cast<ulonglong2*>(&C[base])     = o0;
        *reinterpret_cast<ulonglong2*>(&C[base + 4]) = o1;
    }
}

// ---------------------------------------------------------------------------
// Kernel 3: persistent weight-stationary recurrence, 8-CTA clusters.
// grid = (8 unit-slices, 16 batch-groups); cluster = the 8 slices of a group.
// CTA (sl,g): batches 4g..4g+3, units 64*sl..64*sl+63.
// h exchanged via DSMEM writer-push + 1 cluster barrier per step.
// m replicated per CTA (bitwise identical across the cluster).
// ---------------------------------------------------------------------------
struct Smem {
    float HKs2[UNITS * 64];   // 131072 B: [(k>>2)*256 + u*4 + (k&3)]
    float MKs2[ORDER * 64];   //  32768 B: same packing
    float hbuf[2][4 * UNITS]; //  16384 B: ping-pong h (all 512 units, 4 batches)
    float mbuf[2][4 * ORDER]; //   4096 B: ping-pong m
    float pred[4 * 512];      //   8192 B: transposed partial sums [b][...]
    float he[UNITS];
    float me[ORDER];
    float bt[ORDER];
    float wred[16];
    float xev[4];
};

__global__ void __launch_bounds__(512, 1) __cluster_dims__(8, 1, 1)
recur_kernel(const float* __restrict__ he, const float* __restrict__ me,
             const float* __restrict__ HK, const float* __restrict__ MK,
             const float* __restrict__ AT, const float* __restrict__ BT,
             float* __restrict__ out) {
    extern __shared__ __align__(16) unsigned char smem_raw[];
    Smem* s = reinterpret_cast<Smem*>(smem_raw);

    const int tid = threadIdx.x;
    const int sl  = blockIdx.x;      // unit slice / cluster rank 0..7
    const int g   = blockIdx.y;      // batch group 0..15
    const int us  = sl * 64;

    // ---- load stationary weights (k-pair-packed layout) ----
    for (int i = tid; i < UNITS * 64; i += 512) {
        int k = i >> 6, u = i & 63;
        s->HKs2[(k >> 2) * 256 + u * 4 + (k & 3)] = HK[k * 512 + us + u];
    }
    for (int i = tid; i < ORDER * 64; i += 512) {
        int k = i >> 6, u = i & 63;
        s->MKs2[(k >> 2) * 256 + u * 4 + (k & 3)] = MK[k * 512 + us + u];
    }
    s->he[tid] = he[tid];
    if (tid < 128) { s->me[tid] = me[tid]; s->bt[tid] = BT[tid]; }
    for (int i = tid; i < 2 * 4 * UNITS; i += 512)
        reinterpret_cast<float*>(s->hbuf)[i] = 0.f;
    for (int i = tid; i < 2 * 4 * ORDER; i += 512)
        reinterpret_cast<float*>(s->mbuf)[i] = 0.f;

    // (I + AT) packed into registers: thread (o3 = tid>>2, ks3 = tid&3)
    // am2[j] = pack(A2[kb3+2j][o3], A2[kb3+2j+1][o3])
    const int o3 = tid >> 2, ks3 = tid & 3, kb3 = ks3 * 32;
    unsigned long long am2[16];
#pragma unroll
    for (int j = 0; j < 16; j++) {
        int k = kb3 + 2 * j;
        float a0 = AT[k * 128 + o3]       + (k == o3       ? 1.f : 0.f);
        float a1 = AT[(k + 1) * 128 + o3] + ((k + 1) == o3 ? 1.f : 0.f);
        am2[j] = pack2(a0, a1);
    }
    __syncthreads();

    const int uh = tid & 63, ksh = tid >> 6;   // h-matvec layout
    const int b2 = tid >> 7, j2 = tid & 127;   // u-dot layout

    for (int t = 0; t < SEQ; ++t) {
        const int p = t & 1, pn = p ^ 1;
        const float* hb = s->hbuf[p];
        const float* mo = s->mbuf[p];
        float*       mn = s->mbuf[pn];

        // ---- prefetch (independent of everything in this step) ----
        float2 prex = make_float2(0.f, 0.f);
        if (tid < 128) {
            int b = tid >> 5, ui = tid & 31;
            prex = __ldg(reinterpret_cast<const float2*>(
                &out[(size_t)((4 * g + b) * SEQ + t) * UNITS + us + 2 * ui]));
        }
        if (tid < 4) s->xev[tid] = __ldg(&g_xe[(4 * g + tid) * SEQ + t]);

        // ---- (1) hk partial: acc_b += h_{t-1}[b] . HK  over k in [ksh*64, +64) ----
        unsigned long long a0 = 0, a1 = 0, a2 = 0, a3 = 0;
        {
            const int k0 = ksh * 64;
#pragma unroll
            for (int kk = 0; kk < 64; kk += 4) {
                const int k = k0 + kk;
                ulonglong2 w  = *reinterpret_cast<const ulonglong2*>(&s->HKs2[(k >> 2) * 256 + uh * 4]);
                ulonglong2 h0 = *reinterpret_cast<const ulonglong2*>(&hb[0 * UNITS + k]);
                ulonglong2 h1 = *reinterpret_cast<const ulonglong2*>(&hb[1 * UNITS + k]);
                ulonglong2 h2 = *reinterpret_cast<const ulonglong2*>(&hb[2 * UNITS + k]);
                ulonglong2 h3 = *reinterpret_cast<const ulonglong2*>(&hb[3 * UNITS + k]);
                ffma2(a0, h0.x, w.x); ffma2(a0, h0.y, w.y);
                ffma2(a1, h1.x, w.x); ffma2(a1, h1.y, w.y);
                ffma2(a2, h2.x, w.x); ffma2(a2, h2.y, w.y);
                ffma2(a3, h3.x, w.x); ffma2(a3, h3.y, w.y);
            }
        }

        // ---- (2) u partial: per-warp piece of h·he + m·me ----
        {
            float pu = mo[b2 * ORDER + j2] * s->me[j2];
#pragma unroll
            for (int r = 0; r < 4; r++)
                pu += hb[b2 * UNITS + j2 + 128 * r] * s->he[j2 + 128 * r];
#pragma unroll
            for (int o = 16; o > 0; o >>= 1) pu += __shfl_down_sync(0xffffffffu, pu, o);
            if ((tid & 31) == 0) s->wred[tid >> 5] = pu;
        }

        // ---- (3) m partial: m_{t-1} @ (I+AT), K split 4 ways ----
        {
            unsigned long long c0 = 0, c1 = 0, c2 = 0, c3 = 0;
#pragma unroll
            for (int j = 0; j < 16; j += 2) {
                const int k = kb3 + 2 * j;
                ulonglong2 m0v = *reinterpret_cast<const ulonglong2*>(&mo[0 * ORDER + k]);
                ulonglong2 m1v = *reinterpret_cast<const ulonglong2*>(&mo[1 * ORDER + k]);
                ulonglong2 m2v = *reinterpret_cast<const ulonglong2*>(&mo[2 * ORDER + k]);
                ulonglong2 m3v = *reinterpret_cast<const ulonglong2*>(&mo[3 * ORDER + k]);
                ffma2(c0, m0v.x, am2[j]); ffma2(c0, m0v.y, am2[j + 1]);
                ffma2(c1, m1v.x, am2[j]); ffma2(c1, m1v.y, am2[j + 1]);
                ffma2(c2, m2v.x, am2[j]); ffma2(c2, m2v.y, am2[j + 1]);
                ffma2(c3, m3v.x, am2[j]); ffma2(c3, m3v.y, am2[j + 1]);
            }
            s->pred[0 * 512 + ks3 * 128 + o3] = hsum2(c0);
            s->pred[1 * 512 + ks3 * 128 + o3] = hsum2(c1);
            s->pred[2 * 512 + ks3 * 128 + o3] = hsum2(c2);
            s->pred[3 * 512 + ks3 * 128 + o3] = hsum2(c3);
        }
        __syncthreads();   // S1: wred, xev, m-partials visible

        // ---- (4) m combine: m_t = partials + u * BT ----
        {
            const int b = tid >> 7, o = tid & 127;
            float ub = s->xev[b] + s->wred[b * 4 + 0] + s->wred[b * 4 + 1]
                                 + s->wred[b * 4 + 2] + s->wred[b * 4 + 3];
            float v = ub * s->bt[o];
#pragma unroll
            for (int ks = 0; ks < 4; ks++) v += s->pred[b * 512 + ks * 128 + o];
            mn[b * ORDER + o] = v;
        }
        __syncthreads();   // S2: m_t visible

        // ---- (5) mk partial added to hk accs; store transposed partials ----
        {
            const int k0 = ksh * 16;
#pragma unroll
            for (int kk = 0; kk < 16; kk += 4) {
                const int k = k0 + kk;
                ulonglong2 w   = *reinterpret_cast<const ulonglong2*>(&s->MKs2[(k >> 2) * 256 + uh * 4]);
                ulonglong2 m0v = *reinterpret_cast<const ulonglong2*>(&mn[0 * ORDER + k]);
                ulonglong2 m1v = *reinterpret_cast<const ulonglong2*>(&mn[1 * ORDER + k]);
                ulonglong2 m2v = *reinterpret_cast<const ulonglong2*>(&mn[2 * ORDER + k]);
                ulonglong2 m3v = *reinterpret_cast<const ulonglong2*>(&mn[3 * ORDER + k]);
                ffma2(a0, m0v.x, w.x); ffma2(a0, m0v.y, w.y);
                ffma2(a1, m1v.x, w.x); ffma2(a1, m1v.y, w.y);
                ffma2(a2, m2v.x, w.x); ffma2(a2, m2v.y, w.y);
                ffma2(a3, m3v.x, w.x); ffma2(a3, m3v.y, w.y);
            }
            s->pred[0 * 512 + ksh * 64 + uh] = hsum2(a0);
            s->pred[1 * 512 + ksh * 64 + uh] = hsum2(a1);
            s->pred[2 * 512 + ksh * 64 + uh] = hsum2(a2);
            s->pred[3 * 512 + ksh * 64 + uh] = hsum2(a3);
        }
        __syncthreads();   // S3: h partials visible

        // ---- (6) final: tanh, store out, push h_t slice to all 8 cluster CTAs ----
        if (tid < 128) {
            const int b = tid >> 5, ui = tid & 31;
            const int u0 = 2 * ui;
            float p0 = prex.x, p1 = prex.y;
#pragma unroll
            for (int ks = 0; ks < 8; ks++) {
                p0 += s->pred[b * 512 + ks * 64 + u0];
                p1 += s->pred[b * 512 + ks * 64 + u0 + 1];
            }
            float v0 = tanhf(p0), v1 = tanhf(p1);
            *reinterpret_cast<float2*>(
                &out[(size_t)((4 * g + b) * SEQ + t) * UNITS + us + u0]) = make_float2(v0, v1);
            unsigned int la = (unsigned int)__cvta_generic_to_shared(
                &s->hbuf[pn][b * UNITS + us + u0]);
#pragma unroll
            for (int r = 0; r < 8; r++) {
                unsigned int ra;
                asm("mapa.shared::cluster.u32 %0, %1, %2;" : "=r"(ra) : "r"(la), "r"(r));
                asm volatile("st.shared::cluster.v2.f32 [%0], {%1, %2};"
                             :: "r"(ra), "f"(v0), "f"(v1) : "memory");
            }
        }

        // ---- (7) cluster barrier: release pushes / acquire peers' pushes ----
        asm volatile("barrier.cluster.arrive.aligned;" ::: "memory");
        asm volatile("barrier.cluster.wait.aligned;" ::: "memory");
    }
}

// ---------------------------------------------------------------------------
extern "C" void kernel_launch(void* const* d_in, const int* in_sizes, int n_in,
                              void* d_out, int out_size) {
    const float* x  = (const float*)d_in[0];   // [64,1024,512]
    const float* ie = (const float*)d_in[1];   // [512,1]
    const float* he = (const float*)d_in[2];   // [512,1]
    const float* me = (const float*)d_in[3];   // [128,1]
    const float* IK = (const float*)d_in[4];   // [512,512]
    const float* HK = (const float*)d_in[5];   // [512,512]
    const float* MK = (const float*)d_in[6];   // [128,512]
    const float* AT = (const float*)d_in[7];   // [128,128]
    const float* BT = (const float*)d_in[8];   // [1,128]
    float* out = (float*)d_out;                // [64,1024,512]

    cudaFuncSetAttribute(recur_kernel,
                         cudaFuncAttributeMaxDynamicSharedMemorySize,
                         (int)sizeof(Smem));

    // 1. xe = x @ input_encoders
    xe_kernel<<<(BATCH * SEQ) / 8, 256>>>(x, ie);
    // 2. prex = X @ input_kernel (into d_out), FFMA2 GEMM
    gemm_kernel<<<dim3((BATCH * SEQ) / 128, UNITS / 128), 256>>>(x, IK, out);
    // 3. clustered weight-stationary recurrence
    recur_kernel<<<dim3(8, 16), 512, sizeof(Smem)>>>(he, me, HK, MK, AT, BT, out);
}

// round 11
// speedup vs baseline: 1.6172x; 1.6172x over previous
#include <cuda_runtime.h>

#define SEQ    1024
#define BATCH  64
#define UNITS  512
#define ORDER  128
#define INDIM  512

typedef unsigned long long ull;

// scratch (device globals: no allocation allowed)
__device__ float g_xe[BATCH * SEQ];
__device__ int   g_ctr[16];

// ---------------------------------------------------------------------------
// f32x2 helpers (Blackwell packed fp32 pipe)
// ---------------------------------------------------------------------------
__device__ __forceinline__ void ffma2(ull& d, ull a, ull b) {
    asm("fma.rn.f32x2 %0, %1, %2, %0;" : "+l"(d) : "l"(a), "l"(b));
}
__device__ __forceinline__ ull pack2(float lo, float hi) {
    ull r;
    asm("mov.b64 %0, {%1, %2};" : "=l"(r) : "f"(lo), "f"(hi));
    return r;
}
__device__ __forceinline__ float hsum2(ull v) {
    float lo, hi;
    asm("mov.b64 {%0, %1}, %2;" : "=f"(lo), "=f"(hi) : "l"(v));
    return lo + hi;
}

// ---------------------------------------------------------------------------
// Kernel 1: xe[b,t] = x[b,t,:] @ input_encoders; also reset barrier counters.
// ---------------------------------------------------------------------------
__global__ void __launch_bounds__(256) xe_kernel(const float* __restrict__ x,
                                                 const float* __restrict__ ie) {
    if (blockIdx.x == 0 && threadIdx.x < 16) g_ctr[threadIdx.x] = 0;
    const int warp = threadIdx.x >> 5;
    const int lane = threadIdx.x & 31;
    const int row  = blockIdx.x * 8 + warp;
    const float* xr = x + (size_t)row * INDIM;
    float s = 0.f;
#pragma unroll
    for (int k = lane; k < INDIM; k += 32) s += xr[k] * ie[k];
#pragma unroll
    for (int o = 16; o > 0; o >>= 1) s += __shfl_down_sync(0xffffffffu, s, o);
    if (lane == 0) g_xe[row] = s;
}

// ---------------------------------------------------------------------------
// Kernel 2: prex = X @ input_kernel (M=65536,N=512,K=512) FFMA2, into d_out.
// (proven in R5)
// ---------------------------------------------------------------------------
__global__ void __launch_bounds__(256, 2) gemm_kernel(const float* __restrict__ A,
                                                      const float* __restrict__ B,
                                                      float* __restrict__ C) {
    __shared__ float As[16][132];
    __shared__ float Bs[16][128];
    const int m0  = blockIdx.x * 128;
    const int n0  = blockIdx.y * 128;
    const int tid = threadIdx.x;
    const int tx  = tid & 15;
    const int ty  = tid >> 4;

    ull acc[8][4];
#pragma unroll
    for (int i = 0; i < 8; i++)
#pragma unroll
        for (int j = 0; j < 4; j++) acc[i][j] = 0ull;

    for (int k0 = 0; k0 < 512; k0 += 16) {
#pragma unroll
        for (int i = 0; i < 2; i++) {
            int idx = tid + i * 256;
            int row = idx >> 2;
            int c4  = (idx & 3) << 2;
            float4 v = *reinterpret_cast<const float4*>(&A[(size_t)(m0 + row) * 512 + k0 + c4]);
            As[c4 + 0][row] = v.x; As[c4 + 1][row] = v.y;
            As[c4 + 2][row] = v.z; As[c4 + 3][row] = v.w;
        }
#pragma unroll
        for (int i = 0; i < 2; i++) {
            int idx = tid + i * 256;
            int row = idx >> 5;
            int c4  = (idx & 31) << 2;
            *reinterpret_cast<float4*>(&Bs[row][c4]) =
                *reinterpret_cast<const float4*>(&B[(size_t)(k0 + row) * 512 + n0 + c4]);
        }
        __syncthreads();
#pragma unroll
        for (int k = 0; k < 16; k++) {
            ulonglong2 b01 = *reinterpret_cast<const ulonglong2*>(&Bs[k][tx * 8]);
            ulonglong2 b23 = *reinterpret_cast<const ulonglong2*>(&Bs[k][tx * 8 + 4]);
            float4 ra0 = *reinterpret_cast<const float4*>(&As[k][ty * 8]);
            float4 ra1 = *reinterpret_cast<const float4*>(&As[k][ty * 8 + 4]);
            float rm[8] = {ra0.x, ra0.y, ra0.z, ra0.w, ra1.x, ra1.y, ra1.z, ra1.w};
#pragma unroll
            for (int i = 0; i < 8; i++) {
                ull rp = pack2(rm[i], rm[i]);
                ffma2(acc[i][0], rp, b01.x);
                ffma2(acc[i][1], rp, b01.y);
                ffma2(acc[i][2], rp, b23.x);
                ffma2(acc[i][3], rp, b23.y);
            }
        }
        __syncthreads();
    }
#pragma unroll
    for (int i = 0; i < 8; i++) {
        size_t base = (size_t)(m0 + ty * 8 + i) * 512 + n0 + tx * 8;
        ulonglong2 o0; o0.x = acc[i][0]; o0.y = acc[i][1];
        ulonglong2 o1; o1.x = acc[i][2]; o1.y = acc[i][3];
        *reinterpret_cast<ulonglong2*>(&C[base])     = o0;
        *reinterpret_cast<ulonglong2*>(&C[base + 4]) = o1;
    }
}

// ---------------------------------------------------------------------------
// Kernel 3: weight-stationary recurrence, 128 independent CTAs.
// CTA (sl,g): batches 4g..4g+3, units 64*sl..64*sl+63.
// Exchange = R4 (full h re-read from d_out + atomic barrier, proven).
// Compute  = R5 (FFMA2 phases, proven).
// ---------------------------------------------------------------------------
struct Smem {
    float HKs2[UNITS * 64];   // 131072 B: [(k>>2)*256 + u*4 + (k&3)]
    float MKs2[ORDER * 64];   //  32768 B: same packing
    float hbuf[4][512];       //   8192 B: h_{t-1}, fully rewritten each step
    float mbuf[2][4][128];    //   4096 B: ping-pong m
    float pred[4 * 512];      //   8192 B: partials, reused (m phase / h phase)
    float he[512];
    float me[128];
    float bt[128];
    float wred[16];
    float xev[4];
};

__global__ void __launch_bounds__(512, 1)
recur_kernel(const float* __restrict__ he, const float* __restrict__ me,
             const float* __restrict__ HK, const float* __restrict__ MK,
             const float* __restrict__ AT, const float* __restrict__ BT,
             float* __restrict__ out) {
    extern __shared__ __align__(16) unsigned char smem_raw[];
    Smem* s = reinterpret_cast<Smem*>(smem_raw);

    const int tid = threadIdx.x;
    const int sl  = blockIdx.x;      // unit slice 0..7
    const int g   = blockIdx.y;      // batch group 0..15
    const int us  = sl * 64;

    // ---- stationary weights (R5 layout) ----
    for (int i = tid; i < UNITS * 64; i += 512) {
        int k = i >> 6, u = i & 63;
        s->HKs2[(k >> 2) * 256 + u * 4 + (k & 3)] = HK[k * 512 + us + u];
    }
    for (int i = tid; i < ORDER * 64; i += 512) {
        int k = i >> 6, u = i & 63;
        s->MKs2[(k >> 2) * 256 + u * 4 + (k & 3)] = MK[k * 512 + us + u];
    }
    s->he[tid] = he[tid];
    if (tid < 128) { s->me[tid] = me[tid]; s->bt[tid] = BT[tid]; }
    for (int i = tid; i < 4 * 512; i += 512) (&s->hbuf[0][0])[i] = 0.f;
    for (int i = tid; i < 2 * 4 * 128; i += 512) (&s->mbuf[0][0][0])[i] = 0.f;

    // (I + AT) packed into registers (R5): thread (o3 = tid>>2, ks3 = tid&3)
    const int o3 = tid >> 2, ks3 = tid & 3, kb3 = ks3 * 32;
    ull am2[16];
#pragma unroll
    for (int j = 0; j < 16; j++) {
        int k = kb3 + 2 * j;
        float a0 = AT[k * 128 + o3]       + (k == o3       ? 1.f : 0.f);
        float a1 = AT[(k + 1) * 128 + o3] + ((k + 1) == o3 ? 1.f : 0.f);
        am2[j] = pack2(a0, a1);
    }
    __syncthreads();

    const int uh = tid & 63, ksh = tid >> 6;   // hk/mk layout (R5)
    const int b2 = tid >> 7, j2 = tid & 127;   // u-dot / m-combine layout

    for (int t = 0; t < SEQ; ++t) {
        const int p = t & 1, pn = p ^ 1;

        // ---- prefetch prex (float2, R5-proven) + xe ----
        float2 prex = make_float2(0.f, 0.f);
        if (tid < 128) {
            int b = tid >> 5, ui = tid & 31;
            prex = __ldg(reinterpret_cast<const float2*>(
                &out[(size_t)((4 * g + b) * SEQ + t) * UNITS + us + 2 * ui]));
        }
        if (tid < 4) s->xev[tid] = __ldg(&g_xe[(4 * g + tid) * SEQ + t]);

        // ---- full h gather from d_out (R4-proven scheme) ----
#pragma unroll
        for (int b = 0; b < 4; b++) {
            float v = 0.f;
            if (t > 0)
                v = __ldcg(&out[(size_t)((4 * g + b) * SEQ + (t - 1)) * UNITS + tid]);
            s->hbuf[b][tid] = v;
        }
        __syncthreads();   // S0: h_{t-1} complete

        // ---- (1) hk partial (R5): acc_b over k in [ksh*64, +64) ----
        ull a0 = 0, a1 = 0, a2 = 0, a3 = 0;
        {
            const int k0 = ksh * 64;
#pragma unroll
            for (int kk = 0; kk < 64; kk += 4) {
                const int k = k0 + kk;
                ulonglong2 w  = *reinterpret_cast<const ulonglong2*>(&s->HKs2[(k >> 2) * 256 + uh * 4]);
                ulonglong2 h0 = *reinterpret_cast<const ulonglong2*>(&s->hbuf[0][k]);
                ulonglong2 h1 = *reinterpret_cast<const ulonglong2*>(&s->hbuf[1][k]);
                ulonglong2 h2 = *reinterpret_cast<const ulonglong2*>(&s->hbuf[2][k]);
                ulonglong2 h3 = *reinterpret_cast<const ulonglong2*>(&s->hbuf[3][k]);
                ffma2(a0, h0.x, w.x); ffma2(a0, h0.y, w.y);
                ffma2(a1, h1.x, w.x); ffma2(a1, h1.y, w.y);
                ffma2(a2, h2.x, w.x); ffma2(a2, h2.y, w.y);
                ffma2(a3, h3.x, w.x); ffma2(a3, h3.y, w.y);
            }
        }

        // ---- (2) u-dot partial (R5) ----
        {
            float pu = s->mbuf[p][b2][j2] * s->me[j2];
#pragma unroll
            for (int r = 0; r < 4; r++)
                pu += s->hbuf[b2][j2 + 128 * r] * s->he[j2 + 128 * r];
#pragma unroll
            for (int o = 16; o > 0; o >>= 1)
                pu += __shfl_down_sync(0xffffffffu, pu, o);
            if ((tid & 31) == 0) s->wred[tid >> 5] = pu;
        }

        // ---- (3) m-partial (R5): m_{t-1} @ (I+AT) ----
        {
            const float* mo = &s->mbuf[p][0][0];
            ull c0 = 0, c1 = 0, c2 = 0, c3 = 0;
#pragma unroll
            for (int j = 0; j < 16; j += 2) {
                const int k = kb3 + 2 * j;
                ulonglong2 m0 = *reinterpret_cast<const ulonglong2*>(&mo[0 * 128 + k]);
                ulonglong2 m1 = *reinterpret_cast<const ulonglong2*>(&mo[1 * 128 + k]);
                ulonglong2 m2 = *reinterpret_cast<const ulonglong2*>(&mo[2 * 128 + k]);
                ulonglong2 m3 = *reinterpret_cast<const ulonglong2*>(&mo[3 * 128 + k]);
                ffma2(c0, m0.x, am2[j]); ffma2(c0, m0.y, am2[j + 1]);
                ffma2(c1, m1.x, am2[j]); ffma2(c1, m1.y, am2[j + 1]);
                ffma2(c2, m2.x, am2[j]); ffma2(c2, m2.y, am2[j + 1]);
                ffma2(c3, m3.x, am2[j]); ffma2(c3, m3.y, am2[j + 1]);
            }
            s->pred[0 * 512 + ks3 * 128 + o3] = hsum2(c0);
            s->pred[1 * 512 + ks3 * 128 + o3] = hsum2(c1);
            s->pred[2 * 512 + ks3 * 128 + o3] = hsum2(c2);
            s->pred[3 * 512 + ks3 * 128 + o3] = hsum2(c3);
        }
        __syncthreads();   // S1: wred, xev, m-partials visible

        // ---- (4) m combine (R5): m_t = partials + u * BT ----
        {
            float ubv = s->xev[b2] + s->wred[b2 * 4 + 0] + s->wred[b2 * 4 + 1]
                                   + s->wred[b2 * 4 + 2] + s->wred[b2 * 4 + 3];
            float v = ubv * s->bt[j2];
#pragma unroll
            for (int ks = 0; ks < 4; ks++) v += s->pred[b2 * 512 + ks * 128 + j2];
            s->mbuf[pn][b2][j2] = v;
        }
        __syncthreads();   // S2: m_t visible

        // ---- (5) mk partial (R5), added into same accumulators ----
        {
            const float* mn = &s->mbuf[pn][0][0];
            const int k0 = ksh * 16;
#pragma unroll
            for (int kk = 0; kk < 16; kk += 4) {
                const int k = k0 + kk;
                ulonglong2 w  = *reinterpret_cast<const ulonglong2*>(&s->MKs2[(k >> 2) * 256 + uh * 4]);
                ulonglong2 m0 = *reinterpret_cast<const ulonglong2*>(&mn[0 * 128 + k]);
                ulonglong2 m1 = *reinterpret_cast<const ulonglong2*>(&mn[1 * 128 + k]);
                ulonglong2 m2 = *reinterpret_cast<const ulonglong2*>(&mn[2 * 128 + k]);
                ulonglong2 m3 = *reinterpret_cast<const ulonglong2*>(&mn[3 * 128 + k]);
                ffma2(a0, m0.x, w.x); ffma2(a0, m0.y, w.y);
                ffma2(a1, m1.x, w.x); ffma2(a1, m1.y, w.y);
                ffma2(a2, m2.x, w.x); ffma2(a2, m2.y, w.y);
                ffma2(a3, m3.x, w.x); ffma2(a3, m3.y, w.y);
            }
            s->pred[0 * 512 + ksh * 64 + uh] = hsum2(a0);
            s->pred[1 * 512 + ksh * 64 + uh] = hsum2(a1);
            s->pred[2 * 512 + ksh * 64 + uh] = hsum2(a2);
            s->pred[3 * 512 + ksh * 64 + uh] = hsum2(a3);
        }
        __syncthreads();   // S3: h partials visible

        // ---- (6) final (R5): reduce, tanh, store to out (= h exchange) ----
        if (tid < 128) {
            const int b = tid >> 5, ui = tid & 31;
            const int u0 = 2 * ui;
            float p0 = prex.x, p1 = prex.y;
#pragma unroll
            for (int ks = 0; ks < 8; ks++) {
                p0 += s->pred[b * 512 + ks * 64 + u0];
                p1 += s->pred[b * 512 + ks * 64 + u0 + 1];
            }
            *reinterpret_cast<float2*>(
                &out[(size_t)((4 * g + b) * SEQ + t) * UNITS + us + u0]) =
                make_float2(tanhf(p0), tanhf(p1));
        }

        // ---- per-group barrier (R4-proven verbatim) ----
        __threadfence();
        __syncthreads();
        if (tid == 0) {
            atomicAdd(&g_ctr[g], 1);
            const int target = 8 * (t + 1);
            while (*reinterpret_cast<volatile int*>(&g_ctr[g]) < target) { }
        }
        __syncthreads();
    }
}

// ---------------------------------------------------------------------------
extern "C" void kernel_launch(void* const* d_in, const int* in_sizes, int n_in,
                              void* d_out, int out_size) {
    const float* x  = (const float*)d_in[0];   // [64,1024,512]
    const float* ie = (const float*)d_in[1];   // [512,1]
    const float* he = (const float*)d_in[2];   // [512,1]
    const float* me = (const float*)d_in[3];   // [128,1]
    const float* IK = (const float*)d_in[4];   // [512,512]
    const float* HK = (const float*)d_in[5];   // [512,512]
    const float* MK = (const float*)d_in[6];   // [128,512]
    const float* AT = (const float*)d_in[7];   // [128,128]
    const float* BT = (const float*)d_in[8];   // [1,128]
    float* out = (float*)d_out;                // [64,1024,512]

    cudaFuncSetAttribute(recur_kernel,
                         cudaFuncAttributeMaxDynamicSharedMemorySize,
                         (int)sizeof(Smem));

    xe_kernel<<<(BATCH * SEQ) / 8, 256>>>(x, ie);
    gemm_kernel<<<dim3((BATCH * SEQ) / 128, UNITS / 128), 256>>>(x, IK, out);
    recur_kernel<<<dim3(8, 16), 512, sizeof(Smem)>>>(he, me, HK, MK, AT, BT, out);
}

// round 12
// speedup vs baseline: 1.7142x; 1.0600x over previous
#include <cuda_runtime.h>

#define SEQ    1024
#define BATCH  64
#define UNITS  512
#define ORDER  128
#define INDIM  512

typedef unsigned long long ull;

// scratch (device globals: no allocation allowed)
// Barrier counters padded to 256B stride: distinct L2 slices per group
// (L2 hash uses bits {8,10-27}; 64B-packed counters all hit one slice and
// its atomic ALU serializes 128 arrivals/step + all polling traffic).
__device__ float g_xe[BATCH * SEQ];
__device__ int   g_ctr[16 * 64];

// ---------------------------------------------------------------------------
// f32x2 helpers (Blackwell packed fp32 pipe)
// ---------------------------------------------------------------------------
__device__ __forceinline__ void ffma2(ull& d, ull a, ull b) {
    asm("fma.rn.f32x2 %0, %1, %2, %0;" : "+l"(d) : "l"(a), "l"(b));
}
__device__ __forceinline__ ull pack2(float lo, float hi) {
    ull r;
    asm("mov.b64 %0, {%1, %2};" : "=l"(r) : "f"(lo), "f"(hi));
    return r;
}
__device__ __forceinline__ float hsum2(ull v) {
    float lo, hi;
    asm("mov.b64 {%0, %1}, %2;" : "=f"(lo), "=f"(hi) : "l"(v));
    return lo + hi;
}

// ---------------------------------------------------------------------------
// Kernel 1: xe[b,t] = x[b,t,:] @ input_encoders; also reset barrier counters.
// ---------------------------------------------------------------------------
__global__ void __launch_bounds__(256) xe_kernel(const float* __restrict__ x,
                                                 const float* __restrict__ ie) {
    if (blockIdx.x == 0 && threadIdx.x < 16) g_ctr[threadIdx.x * 64] = 0;
    const int warp = threadIdx.x >> 5;
    const int lane = threadIdx.x & 31;
    const int row  = blockIdx.x * 8 + warp;
    const float* xr = x + (size_t)row * INDIM;
    float s = 0.f;
#pragma unroll
    for (int k = lane; k < INDIM; k += 32) s += xr[k] * ie[k];
#pragma unroll
    for (int o = 16; o > 0; o >>= 1) s += __shfl_down_sync(0xffffffffu, s, o);
    if (lane == 0) g_xe[row] = s;
}

// ---------------------------------------------------------------------------
// Kernel 2: prex = X @ input_kernel (M=65536,N=512,K=512) FFMA2, into d_out.
// (proven in R5/R11)
// ---------------------------------------------------------------------------
__global__ void __launch_bounds__(256, 2) gemm_kernel(const float* __restrict__ A,
                                                      const float* __restrict__ B,
                                                      float* __restrict__ C) {
    __shared__ float As[16][132];
    __shared__ float Bs[16][128];
    const int m0  = blockIdx.x * 128;
    const int n0  = blockIdx.y * 128;
    const int tid = threadIdx.x;
    const int tx  = tid & 15;
    const int ty  = tid >> 4;

    ull acc[8][4];
#pragma unroll
    for (int i = 0; i < 8; i++)
#pragma unroll
        for (int j = 0; j < 4; j++) acc[i][j] = 0ull;

    for (int k0 = 0; k0 < 512; k0 += 16) {
#pragma unroll
        for (int i = 0; i < 2; i++) {
            int idx = tid + i * 256;
            int row = idx >> 2;
            int c4  = (idx & 3) << 2;
            float4 v = *reinterpret_cast<const float4*>(&A[(size_t)(m0 + row) * 512 + k0 + c4]);
            As[c4 + 0][row] = v.x; As[c4 + 1][row] = v.y;
            As[c4 + 2][row] = v.z; As[c4 + 3][row] = v.w;
        }
#pragma unroll
        for (int i = 0; i < 2; i++) {
            int idx = tid + i * 256;
            int row = idx >> 5;
            int c4  = (idx & 31) << 2;
            *reinterpret_cast<float4*>(&Bs[row][c4]) =
                *reinterpret_cast<const float4*>(&B[(size_t)(k0 + row) * 512 + n0 + c4]);
        }
        __syncthreads();
#pragma unroll
        for (int k = 0; k < 16; k++) {
            ulonglong2 b01 = *reinterpret_cast<const ulonglong2*>(&Bs[k][tx * 8]);
            ulonglong2 b23 = *reinterpret_cast<const ulonglong2*>(&Bs[k][tx * 8 + 4]);
            float4 ra0 = *reinterpret_cast<const float4*>(&As[k][ty * 8]);
            float4 ra1 = *reinterpret_cast<const float4*>(&As[k][ty * 8 + 4]);
            float rm[8] = {ra0.x, ra0.y, ra0.z, ra0.w, ra1.x, ra1.y, ra1.z, ra1.w};
#pragma unroll
            for (int i = 0; i < 8; i++) {
                ull rp = pack2(rm[i], rm[i]);
                ffma2(acc[i][0], rp, b01.x);
                ffma2(acc[i][1], rp, b01.y);
                ffma2(acc[i][2], rp, b23.x);
                ffma2(acc[i][3], rp, b23.y);
            }
        }
        __syncthreads();
    }
#pragma unroll
    for (int i = 0; i < 8; i++) {
        size_t base = (size_t)(m0 + ty * 8 + i) * 512 + n0 + tx * 8;
        ulonglong2 o0; o0.x = acc[i][0]; o0.y = acc[i][1];
        ulonglong2 o1; o1.x = acc[i][2]; o1.y = acc[i][3];
        *reinterpret_cast<ulonglong2*>(&C[base])     = o0;
        *reinterpret_cast<ulonglong2*>(&C[base + 4]) = o1;
    }
}

// ---------------------------------------------------------------------------
// Kernel 3: weight-stationary recurrence, 128 independent CTAs.
// CTA (sl,g): batches 4g..4g+3, units 64*sl..64*sl+63.
// Exchange = R4/R11 (h re-read from d_out + padded atomic barrier).
// Compute  = R11 FFMA2 phases; m-partial hoisted above S0 to cover gather.
// ---------------------------------------------------------------------------
struct Smem {
    float HKs2[UNITS * 64];   // 131072 B: [(k>>2)*256 + u*4 + (k&3)]
    float MKs2[ORDER * 64];   //  32768 B: same packing
    float hbuf[4][512];       //   8192 B: h_{t-1}, fully rewritten each step
    float mbuf[2][4][128];    //   4096 B: ping-pong m
    float pred[4 * 512];      //   8192 B: partials, reused (m phase / h phase)
    float he[512];
    float me[128];
    float bt[128];
    float wred[16];
    float xev[4];
};

__global__ void __launch_bounds__(512, 1)
recur_kernel(const float* __restrict__ he, const float* __restrict__ me,
             const float* __restrict__ HK, const float* __restrict__ MK,
             const float* __restrict__ AT, const float* __restrict__ BT,
             float* __restrict__ out) {
    extern __shared__ __align__(16) unsigned char smem_raw[];
    Smem* s = reinterpret_cast<Smem*>(smem_raw);

    const int tid = threadIdx.x;
    const int sl  = blockIdx.x;      // unit slice 0..7
    const int g   = blockIdx.y;      // batch group 0..15
    const int us  = sl * 64;

    // ---- stationary weights ----
    for (int i = tid; i < UNITS * 64; i += 512) {
        int k = i >> 6, u = i & 63;
        s->HKs2[(k >> 2) * 256 + u * 4 + (k & 3)] = HK[k * 512 + us + u];
    }
    for (int i = tid; i < ORDER * 64; i += 512) {
        int k = i >> 6, u = i & 63;
        s->MKs2[(k >> 2) * 256 + u * 4 + (k & 3)] = MK[k * 512 + us + u];
    }
    s->he[tid] = he[tid];
    if (tid < 128) { s->me[tid] = me[tid]; s->bt[tid] = BT[tid]; }
    for (int i = tid; i < 4 * 512; i += 512) (&s->hbuf[0][0])[i] = 0.f;
    for (int i = tid; i < 2 * 4 * 128; i += 512) (&s->mbuf[0][0][0])[i] = 0.f;

    // (I + AT) packed into registers: thread (o3 = tid>>2, ks3 = tid&3)
    const int o3 = tid >> 2, ks3 = tid & 3, kb3 = ks3 * 32;
    ull am2[16];
#pragma unroll
    for (int j = 0; j < 16; j++) {
        int k = kb3 + 2 * j;
        float a0 = AT[k * 128 + o3]       + (k == o3       ? 1.f : 0.f);
        float a1 = AT[(k + 1) * 128 + o3] + ((k + 1) == o3 ? 1.f : 0.f);
        am2[j] = pack2(a0, a1);
    }
    __syncthreads();

    const int uh = tid & 63, ksh = tid >> 6;   // hk/mk layout
    const int b2 = tid >> 7, j2 = tid & 127;   // u-dot / m-combine layout

    for (int t = 0; t < SEQ; ++t) {
        const int p = t & 1, pn = p ^ 1;

        // ---- prefetch prex + xe (consumed at step end / S1) ----
        float2 prex = make_float2(0.f, 0.f);
        if (tid < 128) {
            int b = tid >> 5, ui = tid & 31;
            prex = __ldg(reinterpret_cast<const float2*>(
                &out[(size_t)((4 * g + b) * SEQ + t) * UNITS + us + 2 * ui]));
        }
        if (tid < 4) s->xev[tid] = __ldg(&g_xe[(4 * g + tid) * SEQ + t]);

        // ---- full h gather from d_out (loads in flight while m-partial runs) ----
#pragma unroll
        for (int b = 0; b < 4; b++) {
            float v = 0.f;
            if (t > 0)
                v = __ldcg(&out[(size_t)((4 * g + b) * SEQ + (t - 1)) * UNITS + tid]);
            s->hbuf[b][tid] = v;
        }

        // ---- m-partial (CTA-local): m_{t-1} @ (I+AT), overlaps the gather ----
        {
            const float* mo = &s->mbuf[p][0][0];
            ull c0 = 0, c1 = 0, c2 = 0, c3 = 0;
#pragma unroll
            for (int j = 0; j < 16; j += 2) {
                const int k = kb3 + 2 * j;
                ulonglong2 m0 = *reinterpret_cast<const ulonglong2*>(&mo[0 * 128 + k]);
                ulonglong2 m1 = *reinterpret_cast<const ulonglong2*>(&mo[1 * 128 + k]);
                ulonglong2 m2 = *reinterpret_cast<const ulonglong2*>(&mo[2 * 128 + k]);
                ulonglong2 m3 = *reinterpret_cast<const ulonglong2*>(&mo[3 * 128 + k]);
                ffma2(c0, m0.x, am2[j]); ffma2(c0, m0.y, am2[j + 1]);
                ffma2(c1, m1.x, am2[j]); ffma2(c1, m1.y, am2[j + 1]);
                ffma2(c2, m2.x, am2[j]); ffma2(c2, m2.y, am2[j + 1]);
                ffma2(c3, m3.x, am2[j]); ffma2(c3, m3.y, am2[j + 1]);
            }
            s->pred[0 * 512 + ks3 * 128 + o3] = hsum2(c0);
            s->pred[1 * 512 + ks3 * 128 + o3] = hsum2(c1);
            s->pred[2 * 512 + ks3 * 128 + o3] = hsum2(c2);
            s->pred[3 * 512 + ks3 * 128 + o3] = hsum2(c3);
        }
        __syncthreads();   // S0: h_{t-1} + m-partials visible

        // ---- (1) hk partial: acc_b over k in [ksh*64, +64) ----
        ull a0 = 0, a1 = 0, a2 = 0, a3 = 0;
        {
            const int k0 = ksh * 64;
#pragma unroll
            for (int kk = 0; kk < 64; kk += 4) {
                const int k = k0 + kk;
                ulonglong2 w  = *reinterpret_cast<const ulonglong2*>(&s->HKs2[(k >> 2) * 256 + uh * 4]);
                ulonglong2 h0 = *reinterpret_cast<const ulonglong2*>(&s->hbuf[0][k]);
                ulonglong2 h1 = *reinterpret_cast<const ulonglong2*>(&s->hbuf[1][k]);
                ulonglong2 h2 = *reinterpret_cast<const ulonglong2*>(&s->hbuf[2][k]);
                ulonglong2 h3 = *reinterpret_cast<const ulonglong2*>(&s->hbuf[3][k]);
                ffma2(a0, h0.x, w.x); ffma2(a0, h0.y, w.y);
                ffma2(a1, h1.x, w.x); ffma2(a1, h1.y, w.y);
                ffma2(a2, h2.x, w.x); ffma2(a2, h2.y, w.y);
                ffma2(a3, h3.x, w.x); ffma2(a3, h3.y, w.y);
            }
        }

        // ---- (2) u-dot partial ----
        {
            float pu = s->mbuf[p][b2][j2] * s->me[j2];
#pragma unroll
            for (int r = 0; r < 4; r++)
                pu += s->hbuf[b2][j2 + 128 * r] * s->he[j2 + 128 * r];
#pragma unroll
            for (int o = 16; o > 0; o >>= 1)
                pu += __shfl_down_sync(0xffffffffu, pu, o);
            if ((tid & 31) == 0) s->wred[tid >> 5] = pu;
        }
        __syncthreads();   // S1: wred visible (m-partials already were)

        // ---- (3) m combine: m_t = partials + u * BT ----
        {
            float ubv = s->xev[b2] + s->wred[b2 * 4 + 0] + s->wred[b2 * 4 + 1]
                                   + s->wred[b2 * 4 + 2] + s->wred[b2 * 4 + 3];
            float v = ubv * s->bt[j2];
#pragma unroll
            for (int ks = 0; ks < 4; ks++) v += s->pred[b2 * 512 + ks * 128 + j2];
            s->mbuf[pn][b2][j2] = v;
        }
        __syncthreads();   // S2: m_t visible

        // ---- (4) mk partial, added into same accumulators ----
        {
            const float* mn = &s->mbuf[pn][0][0];
            const int k0 = ksh * 16;
#pragma unroll
            for (int kk = 0; kk < 16; kk += 4) {
                const int k = k0 + kk;
                ulonglong2 w  = *reinterpret_cast<const ulonglong2*>(&s->MKs2[(k >> 2) * 256 + uh * 4]);
                ulonglong2 m0 = *reinterpret_cast<const ulonglong2*>(&mn[0 * 128 + k]);
                ulonglong2 m1 = *reinterpret_cast<const ulonglong2*>(&mn[1 * 128 + k]);
                ulonglong2 m2 = *reinterpret_cast<const ulonglong2*>(&mn[2 * 128 + k]);
                ulonglong2 m3 = *reinterpret_cast<const ulonglong2*>(&mn[3 * 128 + k]);
                ffma2(a0, m0.x, w.x); ffma2(a0, m0.y, w.y);
                ffma2(a1, m1.x, w.x); ffma2(a1, m1.y, w.y);
                ffma2(a2, m2.x, w.x); ffma2(a2, m2.y, w.y);
                ffma2(a3, m3.x, w.x); ffma2(a3, m3.y, w.y);
            }
            s->pred[0 * 512 + ksh * 64 + uh] = hsum2(a0);
            s->pred[1 * 512 + ksh * 64 + uh] = hsum2(a1);
            s->pred[2 * 512 + ksh * 64 + uh] = hsum2(a2);
            s->pred[3 * 512 + ksh * 64 + uh] = hsum2(a3);
        }
        __syncthreads();   // S3: h partials visible

        // ---- (5) final: reduce, tanh, store to out (= h exchange) ----
        if (tid < 128) {
            const int b = tid >> 5, ui = tid & 31;
            const int u0 = 2 * ui;
            float p0 = prex.x, p1 = prex.y;
#pragma unroll
            for (int ks = 0; ks < 8; ks++) {
                p0 += s->pred[b * 512 + ks * 64 + u0];
                p1 += s->pred[b * 512 + ks * 64 + u0 + 1];
            }
            *reinterpret_cast<float2*>(
                &out[(size_t)((4 * g + b) * SEQ + t) * UNITS + us + u0]) =
                make_float2(tanhf(p0), tanhf(p1));
        }

        // ---- per-group barrier (padded counters: one L2 slice per group) ----
        __threadfence();
        __syncthreads();
        if (tid == 0) {
            atomicAdd(&g_ctr[g * 64], 1);
            const int target = 8 * (t + 1);
            while (*reinterpret_cast<volatile int*>(&g_ctr[g * 64]) < target) { }
        }
        __syncthreads();
    }
}

// ---------------------------------------------------------------------------
extern "C" void kernel_launch(void* const* d_in, const int* in_sizes, int n_in,
                              void* d_out, int out_size) {
    const float* x  = (const float*)d_in[0];   // [64,1024,512]
    const float* ie = (const float*)d_in[1];   // [512,1]
    const float* he = (const float*)d_in[2];   // [512,1]
    const float* me = (const float*)d_in[3];   // [128,1]
    const float* IK = (const float*)d_in[4];   // [512,512]
    const float* HK = (const float*)d_in[5];   // [512,512]
    const float* MK = (const float*)d_in[6];   // [128,512]
    const float* AT = (const float*)d_in[7];   // [128,128]
    const float* BT = (const float*)d_in[8];   // [1,128]
    float* out = (float*)d_out;                // [64,1024,512]

    cudaFuncSetAttribute(recur_kernel,
                         cudaFuncAttributeMaxDynamicSharedMemorySize,
                         (int)sizeof(Smem));

    xe_kernel<<<(BATCH * SEQ) / 8, 256>>>(x, ie);
    gemm_kernel<<<dim3((BATCH * SEQ) / 128, UNITS / 128), 256>>>(x, IK, out);
    recur_kernel<<<dim3(8, 16), 512, sizeof(Smem)>>>(he, me, HK, MK, AT, BT, out);
}